// round 1
// baseline (speedup 1.0000x reference)
#include <cuda_runtime.h>
#include <cstdint>
#include <cstdio>

// Conv1d as implicit GEMM on tf32 mma.sync tensor cores.
// out[b, co, l] = sum_{ci,k} w[co,ci,k] * x[b,ci,l+k] + bias[co]
// B=32, Cin=64, L=16384, Cout=64, K=3, Lout=16382, fp32 I/O.

#define CIN   64
#define COUT  64
#define L_IN  16384
#define L_OUT 16382
#define BATCH 32
#define KTAPS 3
#define KDIM  (CIN * KTAPS)   // 192
#define LT    128             // output positions per CTA
#define LDX   136             // smem row stride (floats) for x tile; 136%32==8 -> conflict-free B loads
#define LDW   196             // smem row stride for weights;        196%32==4 -> conflict-free A loads
#define NTHREADS 256

// m16n8k8 tf32 mma, fp32 accumulate
#define MMA_TF32(d, a, b0_, b1_)                                              \
    asm volatile(                                                              \
        "mma.sync.aligned.m16n8k8.row.col.f32.tf32.tf32.f32 "                  \
        "{%0,%1,%2,%3}, {%4,%5,%6,%7}, {%8,%9}, {%0,%1,%2,%3};"                \
        : "+f"((d)[0]), "+f"((d)[1]), "+f"((d)[2]), "+f"((d)[3])               \
        : "r"((a)[0]), "r"((a)[1]), "r"((a)[2]), "r"((a)[3]),                  \
          "r"(b0_), "r"(b1_))

__device__ __forceinline__ uint32_t f32_to_tf32(float f) {
    uint32_t t;
    asm("cvt.rna.tf32.f32 %0, %1;" : "=r"(t) : "f"(f));
    return t;
}

__global__ __launch_bounds__(NTHREADS, 2)
void conv1d_tf32_kernel(const float* __restrict__ x,
                        const float* __restrict__ w,
                        const float* __restrict__ bias,
                        float* __restrict__ out)
{
    extern __shared__ uint32_t smem[];
    uint32_t* XS = smem;                    // [CIN][LDX]  x tile, tf32
    uint32_t* WS = smem + CIN * LDX;        // [COUT][LDW] weights reordered [m][tap*64+ci], tf32

    const int tid  = threadIdx.x;
    const int lane = tid & 31;
    const int wid  = tid >> 5;
    const int g    = lane >> 2;   // group id 0..7
    const int tig  = lane & 3;    // thread-in-group 0..3

    const int tile = blockIdx.x;            // 0..127
    const int b    = blockIdx.y;            // 0..31
    const int l0   = tile * LT;

    // ---- Fill x tile: CIN rows x (LT+2) cols, clamp OOB to 0, cvt to tf32 ----
    {
        const float* xb = x + (size_t)b * CIN * L_IN + l0;
        for (int row = wid; row < CIN; row += 8) {
            const float* xr = xb + (size_t)row * L_IN;
            uint32_t* xs = XS + row * LDX;
            #pragma unroll
            for (int col = lane; col < LT + 2; col += 32) {
                float v = (l0 + col < L_IN) ? xr[col] : 0.0f;
                xs[col] = f32_to_tf32(v);
            }
        }
    }
    // ---- Fill weights: WS[m][tap*64+ci] = w[m][ci][tap], cvt to tf32 ----
    for (int i = tid; i < COUT * KDIM; i += NTHREADS) {
        int m  = i / KDIM;
        int kk = i - m * KDIM;
        int tap = kk >> 6;
        int ci  = kk & 63;
        WS[m * LDW + kk] = f32_to_tf32(w[(m * CIN + ci) * KTAPS + tap]);
    }
    __syncthreads();

    // ---- Warp tiling: 2 (M) x 4 (N). Warp tile = 32 (M) x 32 (N). ----
    const int warp_m = wid & 1;      // 0..1
    const int warp_n = wid >> 1;     // 0..3
    const int mbase  = warp_m * 32;
    const int nbase  = warp_n * 32;

    float acc[2][4][4];
    #pragma unroll
    for (int mt = 0; mt < 2; mt++)
        #pragma unroll
        for (int nt = 0; nt < 4; nt++)
            #pragma unroll
            for (int r = 0; r < 4; r++)
                acc[mt][nt][r] = 0.0f;

    // ---- Main loop: 24 k-steps of 8 (3 taps x 8 ci-chunks) ----
    #pragma unroll
    for (int s = 0; s < KDIM / 8; s++) {
        const int tap = s >> 3;          // 0..2
        const int kb  = (s & 7) * 8;     // ci base within tap

        // A fragments (weights), m16k8 each, 2 m-tiles
        uint32_t a[2][4];
        #pragma unroll
        for (int mt = 0; mt < 2; mt++) {
            const uint32_t* wr = WS + (mbase + mt * 16 + g) * LDW + tap * 64 + kb + tig;
            a[mt][0] = wr[0];
            a[mt][1] = wr[8 * LDW];
            a[mt][2] = wr[4];
            a[mt][3] = wr[8 * LDW + 4];
        }

        // B fragments (x), k8n8 each, 4 n-tiles; fused with mma
        #pragma unroll
        for (int nt = 0; nt < 4; nt++) {
            const uint32_t* xsp = XS + (kb + tig) * LDX + nbase + nt * 8 + g + tap;
            uint32_t b0 = xsp[0];
            uint32_t b1 = xsp[4 * LDX];
            #pragma unroll
            for (int mt = 0; mt < 2; mt++)
                MMA_TF32(acc[mt][nt], a[mt], b0, b1);
        }
    }

    // ---- Epilogue: add bias, store (float2 per c-pair) ----
    #pragma unroll
    for (int mt = 0; mt < 2; mt++) {
        const int m0  = mbase + mt * 16 + g;
        const float bv0 = bias[m0];
        const float bv1 = bias[m0 + 8];
        float* o0 = out + ((size_t)b * COUT + m0) * L_OUT + l0;
        float* o1 = o0 + 8 * (size_t)L_OUT;
        #pragma unroll
        for (int nt = 0; nt < 4; nt++) {
            const int n = nbase + nt * 8 + 2 * tig;
            if (l0 + n < L_OUT) {
                float2 v0 = make_float2(acc[mt][nt][0] + bv0, acc[mt][nt][1] + bv0);
                float2 v1 = make_float2(acc[mt][nt][2] + bv1, acc[mt][nt][3] + bv1);
                *reinterpret_cast<float2*>(o0 + n) = v0;
                *reinterpret_cast<float2*>(o1 + n) = v1;
            }
        }
    }
}

extern "C" void kernel_launch(void* const* d_in, const int* in_sizes, int n_in,
                              void* d_out, int out_size)
{
    const float* x    = (const float*)d_in[0];
    const float* w    = (const float*)d_in[1];
    const float* bias = (const float*)d_in[2];
    float* out        = (float*)d_out;

    const int smem_bytes = (CIN * LDX + COUT * LDW) * 4;  // 84,992 B
    cudaFuncSetAttribute(conv1d_tf32_kernel,
                         cudaFuncAttributeMaxDynamicSharedMemorySize, smem_bytes);

    dim3 grid((L_OUT + LT - 1) / LT, BATCH);   // 128 x 32
    conv1d_tf32_kernel<<<grid, NTHREADS, smem_bytes>>>(x, w, bias, out);
}

// round 2
// speedup vs baseline: 1.0141x; 1.0141x over previous
#include <cuda_runtime.h>
#include <cstdint>
#include <cstdio>

// Conv1d as implicit GEMM on tf32 mma.sync tensor cores.
// out[b, co, l] = sum_{ci,k} w[co,ci,k] * x[b,ci,l+k] + bias[co]
// B=32, Cin=64, L=16384, Cout=64, K=3, Lout=16382, fp32 I/O.

#define CIN   64
#define COUT  64
#define L_IN  16384
#define L_OUT 16382
#define BATCH 32
#define KTAPS 3
#define KDIM  (CIN * KTAPS)   // 192
#define LT    128             // output positions per CTA
#define LDX   136             // smem row stride (floats) for x tile; 136%32==8 -> conflict-free B loads
#define LDW   196             // smem row stride for weights;        196%32==4 -> conflict-free A loads
#define NTHREADS 256

// m16n8k8 tf32 mma, fp32 accumulate
#define MMA_TF32(d, a, b0_, b1_)                                              \
    asm volatile(                                                              \
        "mma.sync.aligned.m16n8k8.row.col.f32.tf32.tf32.f32 "                  \
        "{%0,%1,%2,%3}, {%4,%5,%6,%7}, {%8,%9}, {%0,%1,%2,%3};"                \
        : "+f"((d)[0]), "+f"((d)[1]), "+f"((d)[2]), "+f"((d)[3])               \
        : "r"((a)[0]), "r"((a)[1]), "r"((a)[2]), "r"((a)[3]),                  \
          "r"(b0_), "r"(b1_))

__device__ __forceinline__ uint32_t f32_to_tf32(float f) {
    uint32_t t;
    asm("cvt.rna.tf32.f32 %0, %1;" : "=r"(t) : "f"(f));
    return t;
}

__global__ __launch_bounds__(NTHREADS, 2)
void conv1d_tf32_kernel(const float* __restrict__ x,
                        const float* __restrict__ w,
                        const float* __restrict__ bias,
                        float* __restrict__ out)
{
    extern __shared__ uint32_t smem[];
    uint32_t* XS = smem;                    // [CIN][LDX]  x tile, tf32
    uint32_t* WS = smem + CIN * LDX;        // [COUT][LDW] weights reordered [m][tap*64+ci], tf32

    const int tid  = threadIdx.x;
    const int lane = tid & 31;
    const int wid  = tid >> 5;
    const int g    = lane >> 2;   // group id 0..7
    const int tig  = lane & 3;    // thread-in-group 0..3

    const int tile = blockIdx.x;            // 0..127
    const int b    = blockIdx.y;            // 0..31
    const int l0   = tile * LT;

    // ---- Fill x tile: CIN rows x (LT+2) cols, clamp OOB to 0, cvt to tf32 ----
    {
        const float* xb = x + (size_t)b * CIN * L_IN + l0;
        for (int row = wid; row < CIN; row += 8) {
            const float* xr = xb + (size_t)row * L_IN;
            uint32_t* xs = XS + row * LDX;
            #pragma unroll
            for (int col = lane; col < LT + 2; col += 32) {
                float v = (l0 + col < L_IN) ? xr[col] : 0.0f;
                xs[col] = f32_to_tf32(v);
            }
        }
    }
    // ---- Fill weights: WS[m][tap*64+ci] = w[m][ci][tap], cvt to tf32 ----
    for (int i = tid; i < COUT * KDIM; i += NTHREADS) {
        int m  = i / KDIM;
        int kk = i - m * KDIM;
        int tap = kk >> 6;
        int ci  = kk & 63;
        WS[m * LDW + kk] = f32_to_tf32(w[(m * CIN + ci) * KTAPS + tap]);
    }
    __syncthreads();

    // ---- Warp tiling: 2 (M) x 4 (N). Warp tile = 32 (M) x 32 (N). ----
    const int warp_m = wid & 1;      // 0..1
    const int warp_n = wid >> 1;     // 0..3
    const int mbase  = warp_m * 32;
    const int nbase  = warp_n * 32;

    float acc[2][4][4];
    #pragma unroll
    for (int mt = 0; mt < 2; mt++)
        #pragma unroll
        for (int nt = 0; nt < 4; nt++)
            #pragma unroll
            for (int r = 0; r < 4; r++)
                acc[mt][nt][r] = 0.0f;

    // ---- Main loop: 24 k-steps of 8 (3 taps x 8 ci-chunks) ----
    #pragma unroll
    for (int s = 0; s < KDIM / 8; s++) {
        const int tap = s >> 3;          // 0..2
        const int kb  = (s & 7) * 8;     // ci base within tap

        // A fragments (weights), m16k8 each, 2 m-tiles
        uint32_t a[2][4];
        #pragma unroll
        for (int mt = 0; mt < 2; mt++) {
            const uint32_t* wr = WS + (mbase + mt * 16 + g) * LDW + tap * 64 + kb + tig;
            a[mt][0] = wr[0];
            a[mt][1] = wr[8 * LDW];
            a[mt][2] = wr[4];
            a[mt][3] = wr[8 * LDW + 4];
        }

        // B fragments (x), k8n8 each, 4 n-tiles; fused with mma
        #pragma unroll
        for (int nt = 0; nt < 4; nt++) {
            const uint32_t* xsp = XS + (kb + tig) * LDX + nbase + nt * 8 + g + tap;
            uint32_t b0 = xsp[0];
            uint32_t b1 = xsp[4 * LDX];
            #pragma unroll
            for (int mt = 0; mt < 2; mt++)
                MMA_TF32(acc[mt][nt], a[mt], b0, b1);
        }
    }

    // ---- Epilogue: add bias, store (float2 per c-pair) ----
    #pragma unroll
    for (int mt = 0; mt < 2; mt++) {
        const int m0  = mbase + mt * 16 + g;
        const float bv0 = bias[m0];
        const float bv1 = bias[m0 + 8];
        float* o0 = out + ((size_t)b * COUT + m0) * L_OUT + l0;
        float* o1 = o0 + 8 * (size_t)L_OUT;
        #pragma unroll
        for (int nt = 0; nt < 4; nt++) {
            const int n = nbase + nt * 8 + 2 * tig;
            if (l0 + n < L_OUT) {
                float2 v0 = make_float2(acc[mt][nt][0] + bv0, acc[mt][nt][1] + bv0);
                float2 v1 = make_float2(acc[mt][nt][2] + bv1, acc[mt][nt][3] + bv1);
                *reinterpret_cast<float2*>(o0 + n) = v0;
                *reinterpret_cast<float2*>(o1 + n) = v1;
            }
        }
    }
}

extern "C" void kernel_launch(void* const* d_in, const int* in_sizes, int n_in,
                              void* d_out, int out_size)
{
    const float* x    = (const float*)d_in[0];
    const float* w    = (const float*)d_in[1];
    const float* bias = (const float*)d_in[2];
    float* out        = (float*)d_out;

    const int smem_bytes = (CIN * LDX + COUT * LDW) * 4;  // 84,992 B
    cudaFuncSetAttribute(conv1d_tf32_kernel,
                         cudaFuncAttributeMaxDynamicSharedMemorySize, smem_bytes);

    dim3 grid((L_OUT + LT - 1) / LT, BATCH);   // 128 x 32
    conv1d_tf32_kernel<<<grid, NTHREADS, smem_bytes>>>(x, w, bias, out);
}